// round 6
// baseline (speedup 1.0000x reference)
#include <cuda_runtime.h>
#include <cuda_bf16.h>

#define RESO   128
#define NRAYS  16384
#define NSAMP  192

// Round 6: register diet for 12 blocks/SM (40 regs).
// Density corners are no longer replicated 8x per lane: lane L holds only
// corner (L&7); sigma is assembled with a 3-step shfl_xor butterfly (every
// 8-lane group contains all 8 corners). Frees 7 registers and turns the
// 8-LDG density reload into 1 LDG.

__device__ unsigned g_ray_counter;

__global__ void reset_counter_kernel() { g_ray_counter = 0u; }

__global__ __launch_bounds__(128, 12) void render_kernel(
    const float* __restrict__ origins,
    const float* __restrict__ dirs,
    const float* __restrict__ density,
    const float* __restrict__ sh,
    float* __restrict__ out)
{
    const unsigned FULL = 0xffffffffu;
    const int lane = threadIdx.x & 31;
    // This lane's density corner offset; corner bits: [2]=x(+16384) [1]=y(+128) [0]=z(+1)
    const int off_d = ((lane & 4) ? 16384 : 0) + ((lane & 2) ? 128 : 0) + (lane & 1);
    const bool lx = (lane & 4) != 0, ly = (lane & 2) != 0, lz = (lane & 1) != 0;
    const bool sh_act = lane < 27;

    for (;;) {
        // ---- steal a ray -----------------------------------------------------
        unsigned ray;
        if (lane == 0) ray = atomicAdd(&g_ray_counter, 1u);
        ray = __shfl_sync(FULL, ray, 0);
        if (ray >= NRAYS) break;

        float ox = origins[3*ray+0], oy = origins[3*ray+1], oz = origins[3*ray+2];
        float dx = dirs[3*ray+0],    dy = dirs[3*ray+1],    dz = dirs[3*ray+2];

        // Per-lane SH basis coefficient, lane c -> basis[c % 9].
        float bl = 0.0f;
        {
            const float C0 = 0.28209479177387814f;
            const float C1 = 0.4886025119029199f;
            float b[9];
            b[0] = C0;
            b[1] = -C1 * dy;
            b[2] =  C1 * dz;
            b[3] = -C1 * dx;
            b[4] =  1.0925484305920792f * dx * dy;
            b[5] = -1.0925484305920792f * dy * dz;
            b[6] =  0.31539156525252005f * (2.0f*dz*dz - dx*dx - dy*dy);
            b[7] = -1.0925484305920792f * dx * dz;
            b[8] =  0.5462742152960396f * (dx*dx - dy*dy);
            if (sh_act) bl = b[lane % 9];
        }

        // ---- exact trip count (in-bounds samples form a prefix) -------------
        float tmax = 1e30f;
        if (dx > 0.0f) tmax = fminf(tmax, (127.0f - ox) / dx);
        else if (dx < 0.0f) tmax = fminf(tmax, -ox / dx);
        if (dy > 0.0f) tmax = fminf(tmax, (127.0f - oy) / dy);
        else if (dy < 0.0f) tmax = fminf(tmax, -oy / dy);
        if (dz > 0.0f) tmax = fminf(tmax, (127.0f - oz) / dz);
        else if (dz < 0.0f) tmax = fminf(tmax, -oz / dz);

        int n = (int)floorf(tmax * 2.0f + 0.5f);
        n = max(0, min(n, NSAMP));

        #define INB(s) ({                                                   \
            float _t  = ((float)(s) + 0.5f) * 0.5f;                         \
            float _px = fmaf(_t, dx, ox);                                   \
            float _py = fmaf(_t, dy, oy);                                   \
            float _pz = fmaf(_t, dz, oz);                                   \
            (_px >= 0.0f && _px <= 127.0f &&                                \
             _py >= 0.0f && _py <= 127.0f &&                                \
             _pz >= 0.0f && _pz <= 127.0f); })

        while (n > 0     && !INB(n - 1)) --n;  // pin boundary w/ exact predicate
        while (n < NSAMP &&  INB(n))     ++n;
        #undef INB

        // ---- march ----------------------------------------------------------
        float accum = 0.0f;   // color partials read from lanes 0, 9, 18
        float T     = 1.0f;
        int   prev_cell = -1;
        float dcr = 0.0f;                                // this lane's density corner
        float s0=0,s1=0,s2=0,s3=0,s4=0,s5=0,s6=0,s7=0;   // SH corners (this lane's ch)
        float fs = 0.0f;                                 // float sample counter

        #pragma unroll 1
        for (int s = 0; s < n; ++s, fs += 1.0f) {
            float t  = (fs + 0.5f) * 0.5f;
            float px = fmaf(t, dx, ox);
            float py = fmaf(t, dy, oy);
            float pz = fmaf(t, dz, oz);

            float fx = floorf(px), fy = floorf(py), fz = floorf(pz);
            int ix = min((int)fx, RESO - 2);
            int iy = min((int)fy, RESO - 2);
            int iz = min((int)fz, RESO - 2);
            float ax = px - fx, ay = py - fy, az = pz - fz;

            int cell = (ix * RESO + iy) * RESO + iz;
            if (cell != prev_cell) {            // warp-uniform
                prev_cell = cell;
                dcr = __ldg(density + cell + off_d);     // 1 LDG, 8 addrs/warp
                const float* sp = sh + cell * 27 + lane;
                if (sh_act) {
                    s0 = __ldg(sp);              s1 = __ldg(sp + 27);
                    s2 = __ldg(sp + 128*27);     s3 = __ldg(sp + 129*27);
                    s4 = __ldg(sp + 16384*27);   s5 = __ldg(sp + 16385*27);
                    s6 = __ldg(sp + 16512*27);   s7 = __ldg(sp + 16513*27);
                }
            }

            float bx = 1.0f - ax, by = 1.0f - ay, bz = 1.0f - az;
            float xy00 = bx*by, xy01 = bx*ay, xy10 = ax*by, xy11 = ax*ay;
            float w0 = xy00*bz, w1 = xy00*az, w2 = xy01*bz, w3 = xy01*az;
            float w4 = xy10*bz, w5 = xy10*az, w6 = xy11*bz, w7 = xy11*az;

            // sigma: lane-distributed partial + butterfly over each 8-lane group
            float swx = lx ? (ly ? xy11 : xy10) : (ly ? xy01 : xy00);
            float part = swx * (lz ? az : bz) * dcr;
            part += __shfl_xor_sync(FULL, part, 1);
            part += __shfl_xor_sync(FULL, part, 2);
            part += __shfl_xor_sync(FULL, part, 4);
            float sigma = part;                          // identical in all lanes

            // SH trilerp for this lane's channel
            float shv = w0*s0;
            shv = fmaf(w1,s1,shv); shv = fmaf(w2,s2,shv); shv = fmaf(w3,s3,shv);
            shv = fmaf(w4,s4,shv); shv = fmaf(w5,s5,shv); shv = fmaf(w6,s6,shv);
            shv = fmaf(w7,s7,shv);

            if (sigma > 1e-10f) {               // warp-uniform
                float att = __expf(-0.5f * sigma);
                float wgt = T * (1.0f - att);
                T *= att;

                // Sum shv*bl over lane groups {0..8},{9..17},{18..26}.
                float p = sh_act ? shv * bl : 0.0f;
                float v = p;
                v += __shfl_down_sync(FULL, v, 1);
                v += __shfl_down_sync(FULL, v, 2);
                v += __shfl_down_sync(FULL, v, 4);          // lane b: p[b..b+7]
                v += __shfl_sync(FULL, p, (lane + 8) & 31); // + p[b+8]
                float rgb = fmaxf(v + 0.5f, 0.0f);
                accum = fmaf(wgt, rgb, accum);              // lanes 0/9/18 read
            }
        }

        float r1 = __shfl_sync(FULL, accum, 9);
        float r2 = __shfl_sync(FULL, accum, 18);
        if (lane == 0) {
            out[3*ray+0] = accum + T;
            out[3*ray+1] = r1    + T;
            out[3*ray+2] = r2    + T;
        }
    }
}

extern "C" void kernel_launch(void* const* d_in, const int* in_sizes, int n_in,
                              void* d_out, int out_size)
{
    const float* origins = (const float*)d_in[0];
    const float* dirs    = (const float*)d_in[1];
    const float* density = (const float*)d_in[2];
    const float* sh      = (const float*)d_in[3];
    float* out = (float*)d_out;

    reset_counter_kernel<<<1, 1>>>();
    // 12 blocks/SM target at <=40 regs -> 148*12 = 1776 persistent blocks
    render_kernel<<<1776, 128>>>(origins, dirs, density, sh, out);
}